// round 10
// baseline (speedup 1.0000x reference)
#include <cuda_runtime.h>
#include <cuda_bf16.h>
#include <cfloat>
#include <cstdint>

// ---------------------------------------------------------------------------
// EmbeddingBag mean||max (B=8192 bags over T=409600 tokens, D=128) + Linear
// FUSED single kernel: block-per-bag reduce; the block that completes the
// 64th bag of a 64-bag tile immediately runs that tile's GEMM vs L^T.
//   feature_seq : int32 [T]
//   offset_seq  : int32 [B]   (sorted bag starts, offs[0]==0)
//   W           : f32   [VOCAB, 128]
//   L           : f32   [128, 256]
//   out         : f32   [B, 128] = concat(mean, max) @ L^T
// ---------------------------------------------------------------------------

#define D 128
#define K2 256
#define MAX_B 8192
#define TILE_M 64
#define NTILES (MAX_B / TILE_M)       // 128

__device__ __align__(16) float g_men[MAX_B * K2];   // [B, 256], tf32-rounded
__device__ unsigned g_cnt[NTILES];                  // never reset: (old+1)%64 test

__device__ __forceinline__ float f2tf32r(float f) {
    uint32_t r;
    asm("cvt.rna.tf32.f32 %0, %1;" : "=r"(r) : "f"(f));
    return __uint_as_float(r);
}
__device__ __forceinline__ uint32_t f2tf32u(float f) {
    uint32_t r;
    asm("cvt.rna.tf32.f32 %0, %1;" : "=r"(r) : "f"(f));
    return r;
}

__device__ __forceinline__ void mma_tf32(float c[4],
                                         uint32_t a0, uint32_t a1, uint32_t a2, uint32_t a3,
                                         uint32_t b0, uint32_t b1) {
    asm volatile(
        "mma.sync.aligned.m16n8k8.row.col.f32.tf32.tf32.f32 "
        "{%0,%1,%2,%3}, {%4,%5,%6,%7}, {%8,%9}, {%0,%1,%2,%3};"
        : "+f"(c[0]), "+f"(c[1]), "+f"(c[2]), "+f"(c[3])
        : "r"(a0), "r"(a1), "r"(a2), "r"(a3), "r"(b0), "r"(b1));
}

__device__ __forceinline__ uint32_t smem_addr_u32(const void* p) {
    uint32_t a;
    asm("{ .reg .u64 t; cvta.to.shared.u64 t, %1; cvt.u32.u64 %0, t; }"
        : "=r"(a) : "l"(p));
    return a;
}
__device__ __forceinline__ void cp_async16_cg(void* smem_dst, const void* gmem_src) {
    asm volatile("cp.async.cg.shared.global [%0], [%1], 16;"
                 :: "r"(smem_addr_u32(smem_dst)), "l"(gmem_src));
}
__device__ __forceinline__ void cp_async16_ca(void* smem_dst, const void* gmem_src) {
    asm volatile("cp.async.ca.shared.global [%0], [%1], 16;"
                 :: "r"(smem_addr_u32(smem_dst)), "l"(gmem_src));
}
#define CP_COMMIT() asm volatile("cp.async.commit_group;" ::: "memory")
#define CP_WAIT1()  asm volatile("cp.async.wait_group 1;" ::: "memory")

// GEMM geometry (per tile): M=64, N=64 per half (x2), K=256, BK=32, 2 stages
#define LDA 36
#define STAGE_WORDS ((TILE_M + 64) * LDA)          // 4608 words = 18432 B
#define SMEM_BYTES  (2 * STAGE_WORDS * 4)          // 36864 B (>= K1's 8 KB)

__global__ void __launch_bounds__(256) fused_kernel(
    const int* __restrict__ feat,
    const int* __restrict__ offs,
    const float* __restrict__ W,
    const float* __restrict__ L,
    float* __restrict__ out,
    int T, int B)
{
    __shared__ __align__(16) unsigned char smem_raw[SMEM_BYTES];
    __shared__ int sflag;

    const int bag  = blockIdx.x;
    const int tid  = threadIdx.x;
    const int w    = tid >> 5;
    const int lane = tid & 31;

    // ===================== Phase 1: bag reduce =====================
    const int start = offs[bag];
    const int end   = (bag == B - 1) ? T : offs[bag + 1];
    const int cnt   = end - start;

    const float4* __restrict__ Wv = (const float4*)W;   // row stride = 32 float4

    float4 s = make_float4(0.f, 0.f, 0.f, 0.f);
    float4 m = make_float4(-FLT_MAX, -FLT_MAX, -FLT_MAX, -FLT_MAX);

    const int chunk = (cnt + 7) >> 3;
    const int cs = start + w * chunk;
    const int ce = min(cs + chunk, end);

    int t = cs;
    for (; t + 4 <= ce; t += 4) {
        const int f0 = __ldg(&feat[t + 0]);
        const int f1 = __ldg(&feat[t + 1]);
        const int f2 = __ldg(&feat[t + 2]);
        const int f3 = __ldg(&feat[t + 3]);
        const float4 v0 = __ldg(&Wv[f0 * 32 + lane]);
        const float4 v1 = __ldg(&Wv[f1 * 32 + lane]);
        const float4 v2 = __ldg(&Wv[f2 * 32 + lane]);
        const float4 v3 = __ldg(&Wv[f3 * 32 + lane]);
        s.x += v0.x + v1.x + v2.x + v3.x;
        s.y += v0.y + v1.y + v2.y + v3.y;
        s.z += v0.z + v1.z + v2.z + v3.z;
        s.w += v0.w + v1.w + v2.w + v3.w;
        m.x = fmaxf(m.x, fmaxf(fmaxf(v0.x, v1.x), fmaxf(v2.x, v3.x)));
        m.y = fmaxf(m.y, fmaxf(fmaxf(v0.y, v1.y), fmaxf(v2.y, v3.y)));
        m.z = fmaxf(m.z, fmaxf(fmaxf(v0.z, v1.z), fmaxf(v2.z, v3.z)));
        m.w = fmaxf(m.w, fmaxf(fmaxf(v0.w, v1.w), fmaxf(v2.w, v3.w)));
    }
    const int rem = ce - t;
    if (rem > 0) {
        const int i1 = (rem > 1) ? t + 1 : t;
        const int i2 = (rem > 2) ? t + 2 : t;
        const int f0 = __ldg(&feat[t]);
        const int f1 = __ldg(&feat[i1]);
        const int f2 = __ldg(&feat[i2]);
        const float4 v0 = __ldg(&Wv[f0 * 32 + lane]);
        const float4 v1 = __ldg(&Wv[f1 * 32 + lane]);
        const float4 v2 = __ldg(&Wv[f2 * 32 + lane]);
        const float k1 = (rem > 1) ? 1.f : 0.f;
        const float k2 = (rem > 2) ? 1.f : 0.f;
        s.x += v0.x + k1 * v1.x + k2 * v2.x;
        s.y += v0.y + k1 * v1.y + k2 * v2.y;
        s.z += v0.z + k1 * v1.z + k2 * v2.z;
        s.w += v0.w + k1 * v1.w + k2 * v2.w;
        m.x = fmaxf(m.x, v0.x); m.y = fmaxf(m.y, v0.y);
        m.z = fmaxf(m.z, v0.z); m.w = fmaxf(m.w, v0.w);
        if (rem > 1) {
            m.x = fmaxf(m.x, v1.x); m.y = fmaxf(m.y, v1.y);
            m.z = fmaxf(m.z, v1.z); m.w = fmaxf(m.w, v1.w);
        }
        if (rem > 2) {
            m.x = fmaxf(m.x, v2.x); m.y = fmaxf(m.y, v2.y);
            m.z = fmaxf(m.z, v2.z); m.w = fmaxf(m.w, v2.w);
        }
    }

    {
        float4 (*Ss)[32] = reinterpret_cast<float4(*)[32]>(smem_raw);
        float4 (*Sm)[32] = reinterpret_cast<float4(*)[32]>(smem_raw + 4096);
        Ss[w][lane] = s;
        Sm[w][lane] = m;
    }
    __syncthreads();

    if (tid < 32) {
        float4 (*Ss)[32] = reinterpret_cast<float4(*)[32]>(smem_raw);
        float4 (*Sm)[32] = reinterpret_cast<float4(*)[32]>(smem_raw + 4096);
        float4 rs = Ss[0][lane];
        float4 rm = Sm[0][lane];
#pragma unroll
        for (int i = 1; i < 8; ++i) {
            const float4 a = Ss[i][lane];
            const float4 b = Sm[i][lane];
            rs.x += a.x; rs.y += a.y; rs.z += a.z; rs.w += a.w;
            rm.x = fmaxf(rm.x, b.x); rm.y = fmaxf(rm.y, b.y);
            rm.z = fmaxf(rm.z, b.z); rm.w = fmaxf(rm.w, b.w);
        }
        const float inv = 1.0f / fmaxf((float)cnt, 1.0f);
        float4 mean;
        mean.x = f2tf32r(rs.x * inv); mean.y = f2tf32r(rs.y * inv);
        mean.z = f2tf32r(rs.z * inv); mean.w = f2tf32r(rs.w * inv);
        if (cnt == 0) rm = make_float4(0.f, 0.f, 0.f, 0.f);
        float4 mx;
        mx.x = f2tf32r(rm.x); mx.y = f2tf32r(rm.y);
        mx.z = f2tf32r(rm.z); mx.w = f2tf32r(rm.w);

        float4* mp = (float4*)g_men;                 // row stride = 64 float4
        mp[bag * 64 + lane]      = mean;             // cols [0,128)
        mp[bag * 64 + 32 + lane] = mx;               // cols [128,256)
    }
    __syncthreads();   // g_men stores observed block-wide; smem reusable

    // ============ tile counter: last finisher runs the GEMM ============
    const int tile = bag >> 6;
    if (tid == 0) {
        __threadfence();                             // release: publish g_men rows
        const unsigned old = atomicAdd(&g_cnt[tile], 1u);
        sflag = (((old + 1) & 63u) == 0u) ? 1 : 0;
    }
    __syncthreads();
    if (!sflag) return;
    __threadfence();   // acquire: order subsequent g_men reads after counter obs.

    // ===================== Phase 2: tile GEMM =====================
    // out[tile*64 .. +64, :] = g_men[rows] @ L^T, two 64-col halves.
    uint32_t* sh = reinterpret_cast<uint32_t*>(smem_raw);
    const int wid  = tid >> 5;
    const int wr   = wid >> 1;          // 0..3 (16 rows each)
    const int wc   = wid & 1;           // 0..1 (32 cols each)
    const int gp   = lane >> 2;
    const int tg   = lane & 3;
    const int brow0 = tile * TILE_M;

    const int lr = tid >> 2;            // 0..63
    const int lq = (tid & 3) * 8;       // two float4 at lq, lq+4

#pragma unroll 1
    for (int h = 0; h < 2; ++h) {
        const int bcol0 = h * 64;

        auto load_stage = [&](int k0, int st) {
            uint32_t* As = sh + st * STAGE_WORDS;
            uint32_t* Bs = As + TILE_M * LDA;
            // A from g_men via L2 (bypass L1: producers' stores live in L2)
            cp_async16_cg(&As[lr * LDA + lq],     &g_men[(brow0 + lr) * K2 + k0 + lq]);
            cp_async16_cg(&As[lr * LDA + lq + 4], &g_men[(brow0 + lr) * K2 + k0 + lq + 4]);
            // B from L (read-only input)
            cp_async16_ca(&Bs[lr * LDA + lq],     &L[(bcol0 + lr) * K2 + k0 + lq]);
            cp_async16_ca(&Bs[lr * LDA + lq + 4], &L[(bcol0 + lr) * K2 + k0 + lq + 4]);
            CP_COMMIT();
        };

        float acc[4][4];
#pragma unroll
        for (int j = 0; j < 4; ++j)
#pragma unroll
            for (int v = 0; v < 4; ++v) acc[j][v] = 0.0f;

        load_stage(0, 0);

#pragma unroll
        for (int it = 0; it < 8; ++it) {
            const int st = it & 1;
            if (it + 1 < 8) load_stage((it + 1) * 32, st ^ 1);
            else            CP_COMMIT();
            CP_WAIT1();
            __syncthreads();

            const uint32_t* As = sh + st * STAGE_WORDS;
            const uint32_t* Bs = As + TILE_M * LDA;
#pragma unroll
            for (int ks = 0; ks < 32; ks += 8) {
                const int r = wr * 16 + gp;
                const uint32_t a0 = As[r * LDA + ks + tg];
                const uint32_t a1 = As[(r + 8) * LDA + ks + tg];
                const uint32_t a2 = As[r * LDA + ks + tg + 4];
                const uint32_t a3 = As[(r + 8) * LDA + ks + tg + 4];
#pragma unroll
                for (int nt = 0; nt < 4; ++nt) {
                    const int n = wc * 32 + nt * 8 + gp;
                    const uint32_t b0 = f2tf32u(__uint_as_float(Bs[n * LDA + ks + tg]));
                    const uint32_t b1 = f2tf32u(__uint_as_float(Bs[n * LDA + ks + tg + 4]));
                    mma_tf32(acc[nt], a0, a1, a2, a3, b0, b1);
                }
            }
            __syncthreads();
        }

        // epilogue for this half
#pragma unroll
        for (int nt = 0; nt < 4; ++nt) {
            const int row = brow0 + wr * 16 + gp;
            const int col = bcol0 + wc * 32 + nt * 8 + tg * 2;
            float2* o0 = reinterpret_cast<float2*>(&out[row * 128 + col]);
            float2* o1 = reinterpret_cast<float2*>(&out[(row + 8) * 128 + col]);
            *o0 = make_float2(acc[nt][0], acc[nt][1]);
            *o1 = make_float2(acc[nt][2], acc[nt][3]);
        }
    }
}

// ---------------------------------------------------------------------------
extern "C" void kernel_launch(void* const* d_in, const int* in_sizes, int n_in,
                              void* d_out, int out_size)
{
    const int*   feat = (const int*)d_in[0];
    const int*   offs = (const int*)d_in[1];
    const float* W    = (const float*)d_in[2];
    const float* L    = (const float*)d_in[3];
    float*       out  = (float*)d_out;

    const int T = in_sizes[0];
    const int B = in_sizes[1];

    fused_kernel<<<B, 256>>>(feat, offs, W, L, out, T, B);
}

// round 11
// speedup vs baseline: 1.6581x; 1.6581x over previous
#include <cuda_runtime.h>
#include <cuda_bf16.h>
#include <cfloat>
#include <cstdint>

// ---------------------------------------------------------------------------
// EmbeddingBag mean||max (B=8192 bags over T=409600 tokens, D=128) + Linear
//   feature_seq : int32 [T]
//   offset_seq  : int32 [B]   (sorted bag starts, offs[0]==0)
//   W           : f32   [VOCAB, 128]
//   L           : f32   [128, 256]
//   out         : f32   [B, 128] = concat(mean, max) @ L^T
// ---------------------------------------------------------------------------

#define D 128
#define K2 256
#define MAX_B 8192

__device__ __align__(16) float g_men[MAX_B * K2];   // [B, 256], tf32-rounded
__device__ __align__(16) float g_L32[128 * K2];     // L, tf32-rounded

__device__ __forceinline__ float f2tf32r(float f) {
    uint32_t r;
    asm("cvt.rna.tf32.f32 %0, %1;" : "=r"(r) : "f"(f));
    return __uint_as_float(r);
}

// ============================================================================
// Kernel 1: block-per-bag, 8 warps take contiguous chunks; smem combine.
// Main loop unrolled x8 so the average ~6-token warp chunk completes in ONE
// latency wave (MLP=8). Blocks 0..31 also write tf32-rounded L into g_L32.
// ============================================================================
__global__ void __launch_bounds__(256) bag_reduce_kernel(
    const int* __restrict__ feat,
    const int* __restrict__ offs,
    const float* __restrict__ W,
    const float* __restrict__ L,
    int T, int B)
{
    const int bag  = blockIdx.x;
    const int w    = threadIdx.x >> 5;
    const int lane = threadIdx.x & 31;

    if (bag < 32) {   // side task: round L into g_L32
        const int base = bag * 1024 + threadIdx.x * 4;
        const float4 v = *reinterpret_cast<const float4*>(&L[base]);
        float4 r;
        r.x = f2tf32r(v.x); r.y = f2tf32r(v.y);
        r.z = f2tf32r(v.z); r.w = f2tf32r(v.w);
        *reinterpret_cast<float4*>(&g_L32[base]) = r;
    }

    const int start = offs[bag];
    const int end   = (bag == B - 1) ? T : offs[bag + 1];
    const int cnt   = end - start;

    const float4* __restrict__ Wv = (const float4*)W;   // row stride = 32 float4

    float4 s = make_float4(0.f, 0.f, 0.f, 0.f);
    float4 m = make_float4(-FLT_MAX, -FLT_MAX, -FLT_MAX, -FLT_MAX);

    const int chunk = (cnt + 7) >> 3;
    const int cs = start + w * chunk;
    const int ce = min(cs + chunk, end);

    int t = cs;
    // x8 unroll: 8 gathered rows in flight
    for (; t + 8 <= ce; t += 8) {
        int f[8];
#pragma unroll
        for (int i = 0; i < 8; ++i) f[i] = __ldg(&feat[t + i]);
        float4 v[8];
#pragma unroll
        for (int i = 0; i < 8; ++i) v[i] = __ldg(&Wv[f[i] * 32 + lane]);
#pragma unroll
        for (int i = 0; i < 8; ++i) {
            s.x += v[i].x; s.y += v[i].y; s.z += v[i].z; s.w += v[i].w;
            m.x = fmaxf(m.x, v[i].x); m.y = fmaxf(m.y, v[i].y);
            m.z = fmaxf(m.z, v[i].z); m.w = fmaxf(m.w, v[i].w);
        }
    }
    for (; t + 4 <= ce; t += 4) {
        const int f0 = __ldg(&feat[t + 0]);
        const int f1 = __ldg(&feat[t + 1]);
        const int f2 = __ldg(&feat[t + 2]);
        const int f3 = __ldg(&feat[t + 3]);
        const float4 v0 = __ldg(&Wv[f0 * 32 + lane]);
        const float4 v1 = __ldg(&Wv[f1 * 32 + lane]);
        const float4 v2 = __ldg(&Wv[f2 * 32 + lane]);
        const float4 v3 = __ldg(&Wv[f3 * 32 + lane]);
        s.x += v0.x + v1.x + v2.x + v3.x;
        s.y += v0.y + v1.y + v2.y + v3.y;
        s.z += v0.z + v1.z + v2.z + v3.z;
        s.w += v0.w + v1.w + v2.w + v3.w;
        m.x = fmaxf(m.x, fmaxf(fmaxf(v0.x, v1.x), fmaxf(v2.x, v3.x)));
        m.y = fmaxf(m.y, fmaxf(fmaxf(v0.y, v1.y), fmaxf(v2.y, v3.y)));
        m.z = fmaxf(m.z, fmaxf(fmaxf(v0.z, v1.z), fmaxf(v2.z, v3.z)));
        m.w = fmaxf(m.w, fmaxf(fmaxf(v0.w, v1.w), fmaxf(v2.w, v3.w)));
    }
    // predicated remainder (0..3 tokens) in one latency wave
    const int rem = ce - t;
    if (rem > 0) {
        const int i1 = (rem > 1) ? t + 1 : t;
        const int i2 = (rem > 2) ? t + 2 : t;
        const int f0 = __ldg(&feat[t]);
        const int f1 = __ldg(&feat[i1]);
        const int f2 = __ldg(&feat[i2]);
        const float4 v0 = __ldg(&Wv[f0 * 32 + lane]);
        const float4 v1 = __ldg(&Wv[f1 * 32 + lane]);
        const float4 v2 = __ldg(&Wv[f2 * 32 + lane]);
        const float k1 = (rem > 1) ? 1.f : 0.f;
        const float k2 = (rem > 2) ? 1.f : 0.f;
        s.x += v0.x + k1 * v1.x + k2 * v2.x;
        s.y += v0.y + k1 * v1.y + k2 * v2.y;
        s.z += v0.z + k1 * v1.z + k2 * v2.z;
        s.w += v0.w + k1 * v1.w + k2 * v2.w;
        m.x = fmaxf(m.x, v0.x); m.y = fmaxf(m.y, v0.y);
        m.z = fmaxf(m.z, v0.z); m.w = fmaxf(m.w, v0.w);
        if (rem > 1) {
            m.x = fmaxf(m.x, v1.x); m.y = fmaxf(m.y, v1.y);
            m.z = fmaxf(m.z, v1.z); m.w = fmaxf(m.w, v1.w);
        }
        if (rem > 2) {
            m.x = fmaxf(m.x, v2.x); m.y = fmaxf(m.y, v2.y);
            m.z = fmaxf(m.z, v2.z); m.w = fmaxf(m.w, v2.w);
        }
    }

    __shared__ float4 Ss[8][32];
    __shared__ float4 Sm[8][32];
    Ss[w][lane] = s;
    Sm[w][lane] = m;
    __syncthreads();

    if (threadIdx.x < 32) {
        float4 rs = Ss[0][lane];
        float4 rm = Sm[0][lane];
#pragma unroll
        for (int i = 1; i < 8; ++i) {
            const float4 a = Ss[i][lane];
            const float4 b = Sm[i][lane];
            rs.x += a.x; rs.y += a.y; rs.z += a.z; rs.w += a.w;
            rm.x = fmaxf(rm.x, b.x); rm.y = fmaxf(rm.y, b.y);
            rm.z = fmaxf(rm.z, b.z); rm.w = fmaxf(rm.w, b.w);
        }
        const float inv = 1.0f / fmaxf((float)cnt, 1.0f);
        float4 mean;
        mean.x = f2tf32r(rs.x * inv); mean.y = f2tf32r(rs.y * inv);
        mean.z = f2tf32r(rs.z * inv); mean.w = f2tf32r(rs.w * inv);
        if (cnt == 0) rm = make_float4(0.f, 0.f, 0.f, 0.f);
        float4 mx;
        mx.x = f2tf32r(rm.x); mx.y = f2tf32r(rm.y);
        mx.z = f2tf32r(rm.z); mx.w = f2tf32r(rm.w);

        float4* mp = (float4*)g_men;                 // row stride = 64 float4
        mp[bag * 64 + lane]      = mean;             // cols [0,128)
        mp[bag * 64 + 32 + lane] = mx;               // cols [128,256)
    }
}

// ============================================================================
// Kernel 2: C = men @ L^T, mma.sync m16n8k8 tf32, pre-rounded operands.
// BM=64, BN=64, BK=64 -> only 4 K-iterations; each iteration is
// compute-bound (32 MMAs/warp > L2 load latency). 2-stage cp.async ring.
// grid (128,2) = 256 blocks, 8 warps as 4x2, warp tile 16x32.
// ============================================================================
#define BM 64
#define BN 64
#define BK 64
#define LDA (BK + 4)                   // 68 words
#define NIT (K2 / BK)                  // 4
#define STAGE_WORDS ((BM + BN) * LDA)  // 8704 words
#define GEMM_SMEM_BYTES (2 * STAGE_WORDS * 4)   // 69632

__device__ __forceinline__ void mma_tf32(float c[4],
                                         uint32_t a0, uint32_t a1, uint32_t a2, uint32_t a3,
                                         uint32_t b0, uint32_t b1) {
    asm volatile(
        "mma.sync.aligned.m16n8k8.row.col.f32.tf32.tf32.f32 "
        "{%0,%1,%2,%3}, {%4,%5,%6,%7}, {%8,%9}, {%0,%1,%2,%3};"
        : "+f"(c[0]), "+f"(c[1]), "+f"(c[2]), "+f"(c[3])
        : "r"(a0), "r"(a1), "r"(a2), "r"(a3), "r"(b0), "r"(b1));
}

__device__ __forceinline__ uint32_t smem_addr_u32(const void* p) {
    uint32_t a;
    asm("{ .reg .u64 t; cvta.to.shared.u64 t, %1; cvt.u32.u64 %0, t; }"
        : "=r"(a) : "l"(p));
    return a;
}
__device__ __forceinline__ void cp_async16(void* smem_dst, const void* gmem_src) {
    asm volatile("cp.async.ca.shared.global [%0], [%1], 16;"
                 :: "r"(smem_addr_u32(smem_dst)), "l"(gmem_src));
}
#define CP_COMMIT() asm volatile("cp.async.commit_group;" ::: "memory")
#define CP_WAIT1()  asm volatile("cp.async.wait_group 1;" ::: "memory")

__global__ void __launch_bounds__(256) men_gemm_kernel(
    float* __restrict__ out,
    int B)
{
    extern __shared__ uint32_t sh[];
    const int tid  = threadIdx.x;
    const int wid  = tid >> 5;
    const int lane = tid & 31;
    const int wr   = wid >> 1;          // warp row 0..3 (16 rows each)
    const int wc   = wid & 1;           // warp col 0..1 (32 cols each)
    const int gp   = lane >> 2;
    const int tg   = lane & 3;
    const int brow0 = blockIdx.x * BM;
    const int bcol0 = blockIdx.y * BN;

    // stage loader: 64 rows x 16 k-float4 for A and B -> 4+4 cp.async/thread
    const int lr = tid >> 2;            // 0..63
    const int lq = (tid & 3) * 16;      // quads at lq, lq+4, lq+8, lq+12

    auto load_stage = [&](int k0, int st) {
        uint32_t* As = sh + st * STAGE_WORDS;
        uint32_t* Bs = As + BM * LDA;
        const float* ga = &g_men[(brow0 + lr) * K2 + k0 + lq];
        const float* gb = &g_L32[(bcol0 + lr) * K2 + k0 + lq];
#pragma unroll
        for (int q = 0; q < 16; q += 4) {
            cp_async16(&As[lr * LDA + lq + q], ga + q);
            cp_async16(&Bs[lr * LDA + lq + q], gb + q);
        }
        CP_COMMIT();
    };

    float acc[4][4];
#pragma unroll
    for (int j = 0; j < 4; ++j)
#pragma unroll
        for (int v = 0; v < 4; ++v) acc[j][v] = 0.0f;

    load_stage(0, 0);

#pragma unroll
    for (int it = 0; it < NIT; ++it) {
        const int st = it & 1;
        if (it + 1 < NIT) load_stage((it + 1) * BK, st ^ 1);
        else              CP_COMMIT();          // empty group keeps wait uniform
        CP_WAIT1();
        __syncthreads();

        const uint32_t* As = sh + st * STAGE_WORDS;
        const uint32_t* Bs = As + BM * LDA;
#pragma unroll
        for (int ks = 0; ks < BK; ks += 8) {
            const int r = wr * 16 + gp;
            const uint32_t a0 = As[r * LDA + ks + tg];
            const uint32_t a1 = As[(r + 8) * LDA + ks + tg];
            const uint32_t a2 = As[r * LDA + ks + tg + 4];
            const uint32_t a3 = As[(r + 8) * LDA + ks + tg + 4];
#pragma unroll
            for (int nt = 0; nt < 4; ++nt) {
                const int n = wc * 32 + nt * 8 + gp;
                const uint32_t b0 = Bs[n * LDA + ks + tg];
                const uint32_t b1 = Bs[n * LDA + ks + tg + 4];
                mma_tf32(acc[nt], a0, a1, a2, a3, b0, b1);
            }
        }
        __syncthreads();
    }

    // epilogue
#pragma unroll
    for (int nt = 0; nt < 4; ++nt) {
        const int row = brow0 + wr * 16 + gp;
        const int col = bcol0 + wc * 32 + nt * 8 + tg * 2;
        float2* o0 = reinterpret_cast<float2*>(&out[row * 128 + col]);
        float2* o1 = reinterpret_cast<float2*>(&out[(row + 8) * 128 + col]);
        *o0 = make_float2(acc[nt][0], acc[nt][1]);
        *o1 = make_float2(acc[nt][2], acc[nt][3]);
    }
}

// ---------------------------------------------------------------------------
extern "C" void kernel_launch(void* const* d_in, const int* in_sizes, int n_in,
                              void* d_out, int out_size)
{
    const int*   feat = (const int*)d_in[0];
    const int*   offs = (const int*)d_in[1];
    const float* W    = (const float*)d_in[2];
    const float* L    = (const float*)d_in[3];
    float*       out  = (float*)d_out;

    const int T = in_sizes[0];
    const int B = in_sizes[1];

    cudaFuncSetAttribute(men_gemm_kernel,
                         cudaFuncAttributeMaxDynamicSharedMemorySize,
                         GEMM_SMEM_BYTES);

    bag_reduce_kernel<<<B, 256>>>(feat, offs, W, L, T, B);

    dim3 grid(B / BM, 128 / BN);
    men_gemm_kernel<<<grid, 256, GEMM_SMEM_BYTES>>>(out, B);
}

// round 12
// speedup vs baseline: 1.8438x; 1.1120x over previous
#include <cuda_runtime.h>
#include <cuda_bf16.h>
#include <cfloat>
#include <cstdint>

// ---------------------------------------------------------------------------
// EmbeddingBag mean||max (B=8192 bags over T=409600 tokens, D=128) + Linear
//   feature_seq : int32 [T]
//   offset_seq  : int32 [B]   (sorted bag starts, offs[0]==0)
//   W           : f32   [VOCAB, 128]
//   L           : f32   [128, 256]
//   out         : f32   [B, 128] = concat(mean, max) @ L^T
// ---------------------------------------------------------------------------

#define D 128
#define K2 256
#define MAX_B 8192

__device__ __align__(16) float g_men[MAX_B * K2];   // [B, 256], tf32-rounded
__device__ __align__(16) float g_L32[128 * K2];     // L, tf32-rounded

__device__ __forceinline__ float f2tf32r(float f) {
    uint32_t r;
    asm("cvt.rna.tf32.f32 %0, %1;" : "=r"(r) : "f"(f));
    return __uint_as_float(r);
}

// ============================================================================
// Kernel 1: block-per-bag, 8 warps take contiguous chunks; smem combine.
// x8-unrolled main loop (MLP=8). Blocks 0..31 also write tf32-rounded L.
// ============================================================================
__global__ void __launch_bounds__(256) bag_reduce_kernel(
    const int* __restrict__ feat,
    const int* __restrict__ offs,
    const float* __restrict__ W,
    const float* __restrict__ L,
    int T, int B)
{
    const int bag  = blockIdx.x;
    const int w    = threadIdx.x >> 5;
    const int lane = threadIdx.x & 31;

    if (bag < 32) {   // side task: round L into g_L32
        const int base = bag * 1024 + threadIdx.x * 4;
        const float4 v = *reinterpret_cast<const float4*>(&L[base]);
        float4 r;
        r.x = f2tf32r(v.x); r.y = f2tf32r(v.y);
        r.z = f2tf32r(v.z); r.w = f2tf32r(v.w);
        *reinterpret_cast<float4*>(&g_L32[base]) = r;
    }

    const int start = offs[bag];
    const int end   = (bag == B - 1) ? T : offs[bag + 1];
    const int cnt   = end - start;

    const float4* __restrict__ Wv = (const float4*)W;   // row stride = 32 float4

    float4 s = make_float4(0.f, 0.f, 0.f, 0.f);
    float4 m = make_float4(-FLT_MAX, -FLT_MAX, -FLT_MAX, -FLT_MAX);

    const int chunk = (cnt + 7) >> 3;
    const int cs = start + w * chunk;
    const int ce = min(cs + chunk, end);

    int t = cs;
    for (; t + 8 <= ce; t += 8) {
        int f[8];
#pragma unroll
        for (int i = 0; i < 8; ++i) f[i] = __ldg(&feat[t + i]);
        float4 v[8];
#pragma unroll
        for (int i = 0; i < 8; ++i) v[i] = __ldg(&Wv[f[i] * 32 + lane]);
#pragma unroll
        for (int i = 0; i < 8; ++i) {
            s.x += v[i].x; s.y += v[i].y; s.z += v[i].z; s.w += v[i].w;
            m.x = fmaxf(m.x, v[i].x); m.y = fmaxf(m.y, v[i].y);
            m.z = fmaxf(m.z, v[i].z); m.w = fmaxf(m.w, v[i].w);
        }
    }
    for (; t + 4 <= ce; t += 4) {
        const int f0 = __ldg(&feat[t + 0]);
        const int f1 = __ldg(&feat[t + 1]);
        const int f2 = __ldg(&feat[t + 2]);
        const int f3 = __ldg(&feat[t + 3]);
        const float4 v0 = __ldg(&Wv[f0 * 32 + lane]);
        const float4 v1 = __ldg(&Wv[f1 * 32 + lane]);
        const float4 v2 = __ldg(&Wv[f2 * 32 + lane]);
        const float4 v3 = __ldg(&Wv[f3 * 32 + lane]);
        s.x += v0.x + v1.x + v2.x + v3.x;
        s.y += v0.y + v1.y + v2.y + v3.y;
        s.z += v0.z + v1.z + v2.z + v3.z;
        s.w += v0.w + v1.w + v2.w + v3.w;
        m.x = fmaxf(m.x, fmaxf(fmaxf(v0.x, v1.x), fmaxf(v2.x, v3.x)));
        m.y = fmaxf(m.y, fmaxf(fmaxf(v0.y, v1.y), fmaxf(v2.y, v3.y)));
        m.z = fmaxf(m.z, fmaxf(fmaxf(v0.z, v1.z), fmaxf(v2.z, v3.z)));
        m.w = fmaxf(m.w, fmaxf(fmaxf(v0.w, v1.w), fmaxf(v2.w, v3.w)));
    }
    const int rem = ce - t;
    if (rem > 0) {
        const int i1 = (rem > 1) ? t + 1 : t;
        const int i2 = (rem > 2) ? t + 2 : t;
        const int f0 = __ldg(&feat[t]);
        const int f1 = __ldg(&feat[i1]);
        const int f2 = __ldg(&feat[i2]);
        const float4 v0 = __ldg(&Wv[f0 * 32 + lane]);
        const float4 v1 = __ldg(&Wv[f1 * 32 + lane]);
        const float4 v2 = __ldg(&Wv[f2 * 32 + lane]);
        const float k1 = (rem > 1) ? 1.f : 0.f;
        const float k2 = (rem > 2) ? 1.f : 0.f;
        s.x += v0.x + k1 * v1.x + k2 * v2.x;
        s.y += v0.y + k1 * v1.y + k2 * v2.y;
        s.z += v0.z + k1 * v1.z + k2 * v2.z;
        s.w += v0.w + k1 * v1.w + k2 * v2.w;
        m.x = fmaxf(m.x, v0.x); m.y = fmaxf(m.y, v0.y);
        m.z = fmaxf(m.z, v0.z); m.w = fmaxf(m.w, v0.w);
        if (rem > 1) {
            m.x = fmaxf(m.x, v1.x); m.y = fmaxf(m.y, v1.y);
            m.z = fmaxf(m.z, v1.z); m.w = fmaxf(m.w, v1.w);
        }
        if (rem > 2) {
            m.x = fmaxf(m.x, v2.x); m.y = fmaxf(m.y, v2.y);
            m.z = fmaxf(m.z, v2.z); m.w = fmaxf(m.w, v2.w);
        }
    }

    __shared__ float4 Ss[8][32];
    __shared__ float4 Sm[8][32];
    Ss[w][lane] = s;
    Sm[w][lane] = m;
    __syncthreads();

    if (threadIdx.x < 32) {
        float4 rs = Ss[0][lane];
        float4 rm = Sm[0][lane];
#pragma unroll
        for (int i = 1; i < 8; ++i) {
            const float4 a = Ss[i][lane];
            const float4 b = Sm[i][lane];
            rs.x += a.x; rs.y += a.y; rs.z += a.z; rs.w += a.w;
            rm.x = fmaxf(rm.x, b.x); rm.y = fmaxf(rm.y, b.y);
            rm.z = fmaxf(rm.z, b.z); rm.w = fmaxf(rm.w, b.w);
        }
        const float inv = 1.0f / fmaxf((float)cnt, 1.0f);
        float4 mean;
        mean.x = f2tf32r(rs.x * inv); mean.y = f2tf32r(rs.y * inv);
        mean.z = f2tf32r(rs.z * inv); mean.w = f2tf32r(rs.w * inv);
        if (cnt == 0) rm = make_float4(0.f, 0.f, 0.f, 0.f);
        float4 mx;
        mx.x = f2tf32r(rm.x); mx.y = f2tf32r(rm.y);
        mx.z = f2tf32r(rm.z); mx.w = f2tf32r(rm.w);

        float4* mp = (float4*)g_men;                 // row stride = 64 float4
        mp[bag * 64 + lane]      = mean;             // cols [0,128)
        mp[bag * 64 + 32 + lane] = mx;               // cols [128,256)
    }
}

// ============================================================================
// Kernel 2: C = men @ L^T, mma.sync m16n8k8 tf32, pre-rounded operands.
// SINGLE WAVE: BM=128, BN=64 -> grid (64,2) = 128 blocks on 148 SMs.
// 3-stage cp.async ring (24KB/stage) -> loads run 2 iterations ahead.
// 8 warps as 4x2; warp tile 32x32 = 2 m-tiles x 4 n-tiles.
// ============================================================================
#define BM 128
#define BN 64
#define BK 32
#define LDA (BK + 4)                    // 36 words
#define NIT (K2 / BK)                   // 8
#define STAGES 3
#define STAGE_WORDS ((BM + BN) * LDA)   // 6912 words = 27648 B
#define GEMM_SMEM_BYTES (STAGES * STAGE_WORDS * 4)   // 82944

__device__ __forceinline__ void mma_tf32(float c[4],
                                         uint32_t a0, uint32_t a1, uint32_t a2, uint32_t a3,
                                         uint32_t b0, uint32_t b1) {
    asm volatile(
        "mma.sync.aligned.m16n8k8.row.col.f32.tf32.tf32.f32 "
        "{%0,%1,%2,%3}, {%4,%5,%6,%7}, {%8,%9}, {%0,%1,%2,%3};"
        : "+f"(c[0]), "+f"(c[1]), "+f"(c[2]), "+f"(c[3])
        : "r"(a0), "r"(a1), "r"(a2), "r"(a3), "r"(b0), "r"(b1));
}

__device__ __forceinline__ uint32_t smem_addr_u32(const void* p) {
    uint32_t a;
    asm("{ .reg .u64 t; cvta.to.shared.u64 t, %1; cvt.u32.u64 %0, t; }"
        : "=r"(a) : "l"(p));
    return a;
}
__device__ __forceinline__ void cp_async16(void* smem_dst, const void* gmem_src) {
    asm volatile("cp.async.ca.shared.global [%0], [%1], 16;"
                 :: "r"(smem_addr_u32(smem_dst)), "l"(gmem_src));
}
#define CP_COMMIT() asm volatile("cp.async.commit_group;" ::: "memory")
#define CP_WAIT2()  asm volatile("cp.async.wait_group 2;" ::: "memory")

__global__ void __launch_bounds__(256) men_gemm_kernel(
    float* __restrict__ out,
    int B)
{
    extern __shared__ uint32_t sh[];
    const int tid  = threadIdx.x;
    const int wid  = tid >> 5;
    const int lane = tid & 31;
    const int wr   = wid >> 1;          // warp row 0..3 (32 rows each)
    const int wc   = wid & 1;           // warp col 0..1 (32 cols each)
    const int gp   = lane >> 2;
    const int tg   = lane & 3;
    const int brow0 = blockIdx.x * BM;
    const int bcol0 = blockIdx.y * BN;

    // stage loader: A 128x8 f4 = 1024 slots (4/thread), B 64x8 f4 = 512 (2/thread)
    auto load_stage = [&](int k0, int st) {
        uint32_t* As = sh + st * STAGE_WORDS;
        uint32_t* Bs = As + BM * LDA;
#pragma unroll
        for (int q = 0; q < 4; ++q) {
            const int slot = tid * 4 + q;          // 0..1023
            const int r  = slot >> 3;              // 0..127
            const int kq = (slot & 7) * 4;
            cp_async16(&As[r * LDA + kq], &g_men[(brow0 + r) * K2 + k0 + kq]);
        }
#pragma unroll
        for (int q = 0; q < 2; ++q) {
            const int slot = tid * 2 + q;          // 0..511
            const int n  = slot >> 3;              // 0..63
            const int kq = (slot & 7) * 4;
            cp_async16(&Bs[n * LDA + kq], &g_L32[(bcol0 + n) * K2 + k0 + kq]);
        }
        CP_COMMIT();
    };

    float acc[2][4][4];
#pragma unroll
    for (int i = 0; i < 2; ++i)
#pragma unroll
        for (int j = 0; j < 4; ++j)
#pragma unroll
            for (int v = 0; v < 4; ++v) acc[i][j][v] = 0.0f;

    // prologue: 2 stages in flight
    load_stage(0 * BK, 0);
    load_stage(1 * BK, 1);

#pragma unroll
    for (int it = 0; it < NIT; ++it) {
        const int st = it % STAGES;
        if (it + 2 < NIT) load_stage((it + 2) * BK, (it + 2) % STAGES);
        else              CP_COMMIT();          // empty group keeps wait uniform
        CP_WAIT2();                             // stage `it` complete
        __syncthreads();

        const uint32_t* As = sh + st * STAGE_WORDS;
        const uint32_t* Bs = As + BM * LDA;
#pragma unroll
        for (int ks = 0; ks < BK; ks += 8) {
            uint32_t bf[4][2];
#pragma unroll
            for (int nt = 0; nt < 4; ++nt) {
                const int n = wc * 32 + nt * 8 + gp;
                bf[nt][0] = Bs[n * LDA + ks + tg];
                bf[nt][1] = Bs[n * LDA + ks + tg + 4];
            }
#pragma unroll
            for (int mt = 0; mt < 2; ++mt) {
                const int r = wr * 32 + mt * 16 + gp;
                const uint32_t a0 = As[r * LDA + ks + tg];
                const uint32_t a1 = As[(r + 8) * LDA + ks + tg];
                const uint32_t a2 = As[r * LDA + ks + tg + 4];
                const uint32_t a3 = As[(r + 8) * LDA + ks + tg + 4];
#pragma unroll
                for (int nt = 0; nt < 4; ++nt)
                    mma_tf32(acc[mt][nt], a0, a1, a2, a3, bf[nt][0], bf[nt][1]);
            }
        }
        __syncthreads();
    }

    // epilogue
#pragma unroll
    for (int mt = 0; mt < 2; ++mt) {
#pragma unroll
        for (int nt = 0; nt < 4; ++nt) {
            const int row = brow0 + wr * 32 + mt * 16 + gp;
            const int col = bcol0 + wc * 32 + nt * 8 + tg * 2;
            float2* o0 = reinterpret_cast<float2*>(&out[row * 128 + col]);
            float2* o1 = reinterpret_cast<float2*>(&out[(row + 8) * 128 + col]);
            *o0 = make_float2(acc[mt][nt][0], acc[mt][nt][1]);
            *o1 = make_float2(acc[mt][nt][2], acc[mt][nt][3]);
        }
    }
}

// ---------------------------------------------------------------------------
extern "C" void kernel_launch(void* const* d_in, const int* in_sizes, int n_in,
                              void* d_out, int out_size)
{
    const int*   feat = (const int*)d_in[0];
    const int*   offs = (const int*)d_in[1];
    const float* W    = (const float*)d_in[2];
    const float* L    = (const float*)d_in[3];
    float*       out  = (float*)d_out;

    const int T = in_sizes[0];
    const int B = in_sizes[1];

    cudaFuncSetAttribute(men_gemm_kernel,
                         cudaFuncAttributeMaxDynamicSharedMemorySize,
                         GEMM_SMEM_BYTES);

    bag_reduce_kernel<<<B, 256>>>(feat, offs, W, L, T, B);

    dim3 grid(B / BM, 128 / BN);
    men_gemm_kernel<<<grid, 256, GEMM_SMEM_BYTES>>>(out, B);
}

// round 13
// speedup vs baseline: 1.8454x; 1.0009x over previous
#include <cuda_runtime.h>
#include <cuda_bf16.h>
#include <cfloat>
#include <cstdint>

// ---------------------------------------------------------------------------
// EmbeddingBag mean||max (B=8192 bags over T=409600 tokens, D=128) + Linear
//   feature_seq : int32 [T]
//   offset_seq  : int32 [B]   (sorted bag starts, offs[0]==0)
//   W           : f32   [VOCAB, 128]
//   L           : f32   [128, 256]
//   out         : f32   [B, 128] = concat(mean, max) @ L^T
// ---------------------------------------------------------------------------

#define D 128
#define K2 256
#define MAX_B 8192

__device__ __align__(16) float g_men[MAX_B * K2];   // [B, 256], tf32-rounded
__device__ __align__(16) float g_L32[128 * K2];     // L, tf32-rounded

__device__ __forceinline__ float f2tf32r(float f) {
    uint32_t r;
    asm("cvt.rna.tf32.f32 %0, %1;" : "=r"(r) : "f"(f));
    return __uint_as_float(r);
}

// ============================================================================
// Kernel 1: block-per-bag. Bag indices are STAGED IN SMEM (one coalesced
// sweep) so the gather loop reads indices at LDS latency, not L2 latency.
// 8 warps take contiguous chunks; x8-unrolled gather (MLP=8); smem combine.
// Blocks 0..31 also write tf32-rounded L into g_L32.
// ============================================================================
#define SEG 2048   // indices staged per segment (8KB)

__global__ void __launch_bounds__(256) bag_reduce_kernel(
    const int* __restrict__ feat,
    const int* __restrict__ offs,
    const float* __restrict__ W,
    const float* __restrict__ L,
    int T, int B)
{
    __shared__ int s_idx[SEG];
    __shared__ float4 Ss[8][32];
    __shared__ float4 Sm[8][32];

    const int bag  = blockIdx.x;
    const int tid  = threadIdx.x;
    const int w    = tid >> 5;
    const int lane = tid & 31;

    if (bag < 32) {   // side task: round L into g_L32
        const int base = bag * 1024 + tid * 4;
        const float4 v = *reinterpret_cast<const float4*>(&L[base]);
        float4 r;
        r.x = f2tf32r(v.x); r.y = f2tf32r(v.y);
        r.z = f2tf32r(v.z); r.w = f2tf32r(v.w);
        *reinterpret_cast<float4*>(&g_L32[base]) = r;
    }

    const int start = offs[bag];
    const int end   = (bag == B - 1) ? T : offs[bag + 1];
    const int cnt   = end - start;

    const float4* __restrict__ Wv = (const float4*)W;   // row stride = 32 float4

    float4 s = make_float4(0.f, 0.f, 0.f, 0.f);
    float4 m = make_float4(-FLT_MAX, -FLT_MAX, -FLT_MAX, -FLT_MAX);

    for (int seg = start; seg < end; seg += SEG) {
        const int seglen = min(SEG, end - seg);

        // coalesced index stage
        for (int i = tid; i < seglen; i += 256) s_idx[i] = feat[seg + i];
        __syncthreads();

        const int chunk = (seglen + 7) >> 3;
        const int cs = w * chunk;
        const int ce = min(cs + chunk, seglen);

        int t = cs;
        for (; t + 8 <= ce; t += 8) {
            int f[8];
#pragma unroll
            for (int i = 0; i < 8; ++i) f[i] = s_idx[t + i];
            float4 v[8];
#pragma unroll
            for (int i = 0; i < 8; ++i) v[i] = __ldg(&Wv[f[i] * 32 + lane]);
#pragma unroll
            for (int i = 0; i < 8; ++i) {
                s.x += v[i].x; s.y += v[i].y; s.z += v[i].z; s.w += v[i].w;
                m.x = fmaxf(m.x, v[i].x); m.y = fmaxf(m.y, v[i].y);
                m.z = fmaxf(m.z, v[i].z); m.w = fmaxf(m.w, v[i].w);
            }
        }
        for (; t + 4 <= ce; t += 4) {
            const int f0 = s_idx[t + 0];
            const int f1 = s_idx[t + 1];
            const int f2 = s_idx[t + 2];
            const int f3 = s_idx[t + 3];
            const float4 v0 = __ldg(&Wv[f0 * 32 + lane]);
            const float4 v1 = __ldg(&Wv[f1 * 32 + lane]);
            const float4 v2 = __ldg(&Wv[f2 * 32 + lane]);
            const float4 v3 = __ldg(&Wv[f3 * 32 + lane]);
            s.x += v0.x + v1.x + v2.x + v3.x;
            s.y += v0.y + v1.y + v2.y + v3.y;
            s.z += v0.z + v1.z + v2.z + v3.z;
            s.w += v0.w + v1.w + v2.w + v3.w;
            m.x = fmaxf(m.x, fmaxf(fmaxf(v0.x, v1.x), fmaxf(v2.x, v3.x)));
            m.y = fmaxf(m.y, fmaxf(fmaxf(v0.y, v1.y), fmaxf(v2.y, v3.y)));
            m.z = fmaxf(m.z, fmaxf(fmaxf(v0.z, v1.z), fmaxf(v2.z, v3.z)));
            m.w = fmaxf(m.w, fmaxf(fmaxf(v0.w, v1.w), fmaxf(v2.w, v3.w)));
        }
        // predicated remainder (0..3 tokens) in one latency wave
        const int rem = ce - t;
        if (rem > 0) {
            const int i1 = (rem > 1) ? t + 1 : t;
            const int i2 = (rem > 2) ? t + 2 : t;
            const int f0 = s_idx[t];
            const int f1 = s_idx[i1];
            const int f2 = s_idx[i2];
            const float4 v0 = __ldg(&Wv[f0 * 32 + lane]);
            const float4 v1 = __ldg(&Wv[f1 * 32 + lane]);
            const float4 v2 = __ldg(&Wv[f2 * 32 + lane]);
            const float k1 = (rem > 1) ? 1.f : 0.f;
            const float k2 = (rem > 2) ? 1.f : 0.f;
            s.x += v0.x + k1 * v1.x + k2 * v2.x;
            s.y += v0.y + k1 * v1.y + k2 * v2.y;
            s.z += v0.z + k1 * v1.z + k2 * v2.z;
            s.w += v0.w + k1 * v1.w + k2 * v2.w;
            m.x = fmaxf(m.x, v0.x); m.y = fmaxf(m.y, v0.y);
            m.z = fmaxf(m.z, v0.z); m.w = fmaxf(m.w, v0.w);
            if (rem > 1) {
                m.x = fmaxf(m.x, v1.x); m.y = fmaxf(m.y, v1.y);
                m.z = fmaxf(m.z, v1.z); m.w = fmaxf(m.w, v1.w);
            }
            if (rem > 2) {
                m.x = fmaxf(m.x, v2.x); m.y = fmaxf(m.y, v2.y);
                m.z = fmaxf(m.z, v2.z); m.w = fmaxf(m.w, v2.w);
            }
        }
        __syncthreads();   // before next segment overwrites s_idx
    }

    Ss[w][lane] = s;
    Sm[w][lane] = m;
    __syncthreads();

    if (tid < 32) {
        float4 rs = Ss[0][lane];
        float4 rm = Sm[0][lane];
#pragma unroll
        for (int i = 1; i < 8; ++i) {
            const float4 a = Ss[i][lane];
            const float4 b = Sm[i][lane];
            rs.x += a.x; rs.y += a.y; rs.z += a.z; rs.w += a.w;
            rm.x = fmaxf(rm.x, b.x); rm.y = fmaxf(rm.y, b.y);
            rm.z = fmaxf(rm.z, b.z); rm.w = fmaxf(rm.w, b.w);
        }
        const float inv = 1.0f / fmaxf((float)cnt, 1.0f);
        float4 mean;
        mean.x = f2tf32r(rs.x * inv); mean.y = f2tf32r(rs.y * inv);
        mean.z = f2tf32r(rs.z * inv); mean.w = f2tf32r(rs.w * inv);
        if (cnt == 0) rm = make_float4(0.f, 0.f, 0.f, 0.f);
        float4 mx;
        mx.x = f2tf32r(rm.x); mx.y = f2tf32r(rm.y);
        mx.z = f2tf32r(rm.z); mx.w = f2tf32r(rm.w);

        float4* mp = (float4*)g_men;                 // row stride = 64 float4
        mp[bag * 64 + lane]      = mean;             // cols [0,128)
        mp[bag * 64 + 32 + lane] = mx;               // cols [128,256)
    }
}

// ============================================================================
// Kernel 2: C = men @ L^T, mma.sync m16n8k8 tf32, pre-rounded operands.
// SINGLE WAVE: BM=128, BN=64 -> grid (64,2) = 128 blocks.
// 512 threads = 16 warps (4x4; warp tile 32x16) for latency hiding.
// 3-stage cp.async ring, loads run 2 iterations ahead.
// ============================================================================
#define BM 128
#define BN 64
#define BK 32
#define LDA (BK + 4)                    // 36 words
#define NIT (K2 / BK)                   // 8
#define STAGES 3
#define STAGE_WORDS ((BM + BN) * LDA)   // 6912 words = 27648 B
#define GEMM_SMEM_BYTES (STAGES * STAGE_WORDS * 4)   // 82944

__device__ __forceinline__ void mma_tf32(float c[4],
                                         uint32_t a0, uint32_t a1, uint32_t a2, uint32_t a3,
                                         uint32_t b0, uint32_t b1) {
    asm volatile(
        "mma.sync.aligned.m16n8k8.row.col.f32.tf32.tf32.f32 "
        "{%0,%1,%2,%3}, {%4,%5,%6,%7}, {%8,%9}, {%0,%1,%2,%3};"
        : "+f"(c[0]), "+f"(c[1]), "+f"(c[2]), "+f"(c[3])
        : "r"(a0), "r"(a1), "r"(a2), "r"(a3), "r"(b0), "r"(b1));
}

__device__ __forceinline__ uint32_t smem_addr_u32(const void* p) {
    uint32_t a;
    asm("{ .reg .u64 t; cvta.to.shared.u64 t, %1; cvt.u32.u64 %0, t; }"
        : "=r"(a) : "l"(p));
    return a;
}
__device__ __forceinline__ void cp_async16(void* smem_dst, const void* gmem_src) {
    asm volatile("cp.async.ca.shared.global [%0], [%1], 16;"
                 :: "r"(smem_addr_u32(smem_dst)), "l"(gmem_src));
}
#define CP_COMMIT() asm volatile("cp.async.commit_group;" ::: "memory")
#define CP_WAIT2()  asm volatile("cp.async.wait_group 2;" ::: "memory")

__global__ void __launch_bounds__(512) men_gemm_kernel(
    float* __restrict__ out,
    int B)
{
    extern __shared__ uint32_t sh[];
    const int tid  = threadIdx.x;
    const int wid  = tid >> 5;
    const int lane = tid & 31;
    const int wr   = wid >> 2;          // warp row 0..3 (32 rows each)
    const int wc   = wid & 3;           // warp col 0..3 (16 cols each)
    const int gp   = lane >> 2;
    const int tg   = lane & 3;
    const int brow0 = blockIdx.x * BM;
    const int bcol0 = blockIdx.y * BN;

    // stage loader: A 128x8 f4 = 1024 slots (2/thread), B 64x8 = 512 (1/thread)
    auto load_stage = [&](int k0, int st) {
        uint32_t* As = sh + st * STAGE_WORDS;
        uint32_t* Bs = As + BM * LDA;
#pragma unroll
        for (int q = 0; q < 2; ++q) {
            const int slot = tid * 2 + q;          // 0..1023
            const int r  = slot >> 3;              // 0..127
            const int kq = (slot & 7) * 4;
            cp_async16(&As[r * LDA + kq], &g_men[(brow0 + r) * K2 + k0 + kq]);
        }
        {
            const int n  = tid >> 3;               // 0..63
            const int kq = (tid & 7) * 4;
            cp_async16(&Bs[n * LDA + kq], &g_L32[(bcol0 + n) * K2 + k0 + kq]);
        }
        CP_COMMIT();
    };

    float acc[2][2][4];
#pragma unroll
    for (int i = 0; i < 2; ++i)
#pragma unroll
        for (int j = 0; j < 2; ++j)
#pragma unroll
            for (int v = 0; v < 4; ++v) acc[i][j][v] = 0.0f;

    // prologue: 2 stages in flight
    load_stage(0 * BK, 0);
    load_stage(1 * BK, 1);

#pragma unroll
    for (int it = 0; it < NIT; ++it) {
        const int st = it % STAGES;
        if (it + 2 < NIT) load_stage((it + 2) * BK, (it + 2) % STAGES);
        else              CP_COMMIT();          // empty group keeps wait uniform
        CP_WAIT2();                             // stage `it` complete
        __syncthreads();

        const uint32_t* As = sh + st * STAGE_WORDS;
        const uint32_t* Bs = As + BM * LDA;
#pragma unroll
        for (int ks = 0; ks < BK; ks += 8) {
            uint32_t bf[2][2];
#pragma unroll
            for (int nt = 0; nt < 2; ++nt) {
                const int n = wc * 16 + nt * 8 + gp;
                bf[nt][0] = Bs[n * LDA + ks + tg];
                bf[nt][1] = Bs[n * LDA + ks + tg + 4];
            }
#pragma unroll
            for (int mt = 0; mt < 2; ++mt) {
                const int r = wr * 32 + mt * 16 + gp;
                const uint32_t a0 = As[r * LDA + ks + tg];
                const uint32_t a1 = As[(r + 8) * LDA + ks + tg];
                const uint32_t a2 = As[r * LDA + ks + tg + 4];
                const uint32_t a3 = As[(r + 8) * LDA + ks + tg + 4];
#pragma unroll
                for (int nt = 0; nt < 2; ++nt)
                    mma_tf32(acc[mt][nt], a0, a1, a2, a3, bf[nt][0], bf[nt][1]);
            }
        }
        __syncthreads();
    }

    // epilogue
#pragma unroll
    for (int mt = 0; mt < 2; ++mt) {
#pragma unroll
        for (int nt = 0; nt < 2; ++nt) {
            const int row = brow0 + wr * 32 + mt * 16 + gp;
            const int col = bcol0 + wc * 16 + nt * 8 + tg * 2;
            float2* o0 = reinterpret_cast<float2*>(&out[row * 128 + col]);
            float2* o1 = reinterpret_cast<float2*>(&out[(row + 8) * 128 + col]);
            *o0 = make_float2(acc[mt][nt][0], acc[mt][nt][1]);
            *o1 = make_float2(acc[mt][nt][2], acc[mt][nt][3]);
        }
    }
}

// ---------------------------------------------------------------------------
extern "C" void kernel_launch(void* const* d_in, const int* in_sizes, int n_in,
                              void* d_out, int out_size)
{
    const int*   feat = (const int*)d_in[0];
    const int*   offs = (const int*)d_in[1];
    const float* W    = (const float*)d_in[2];
    const float* L    = (const float*)d_in[3];
    float*       out  = (float*)d_out;

    const int T = in_sizes[0];
    const int B = in_sizes[1];

    cudaFuncSetAttribute(men_gemm_kernel,
                         cudaFuncAttributeMaxDynamicSharedMemorySize,
                         GEMM_SMEM_BYTES);

    bag_reduce_kernel<<<B, 256>>>(feat, offs, W, L, T, B);

    dim3 grid(B / BM, 128 / BN);
    men_gemm_kernel<<<grid, 512, GEMM_SMEM_BYTES>>>(out, B);
}